// round 1
// baseline (speedup 1.0000x reference)
#include <cuda_runtime.h>
#include <math.h>

#define NBATCH 16
#define NA 3
#define SDIM 80
#define NCLS 80
#define NCH 85           // NC + 5
#define PLANE (SDIM*SDIM)        // 6400
#define NCELLS (NBATCH*NA*SDIM*SDIM)  // 307200
#define EPSF 1e-7f

// Scratch (no dynamic allocation allowed)
__device__ int    g_win[NCELLS];
__device__ double g_acc[4];   // 0: obj sum, 1: cls sum, 2: box sum, 3: nobj

// ---------------------------------------------------------------------------
__global__ void clear_kernel() {
    int i = blockIdx.x * blockDim.x + threadIdx.x;
    if (i < NCELLS) g_win[i] = -1;
    if (i < 4)      g_acc[i] = 0.0;
}

// ---------------------------------------------------------------------------
// One thread per target: compute anchor matches + neighbor offsets, scatter
// winner id (n*5+k) with atomicMax => replicates JAX last-write-wins order.
__global__ void scatter_kernel(const float* __restrict__ tg, int N) {
    int n = blockIdx.x * blockDim.x + threadIdx.x;
    if (n >= N) return;
    const float* t = tg + n * 6;
    int   b  = (int)t[0];
    float bx = t[2], by = t[3], bw = t[4], bh = t[5];

    float gx = bx * SDIM, gy = by * SDIM;
    int ib = (int)floorf(gx), jb = (int)floorf(gy);
    float oi = gx - floorf(gx), oj = gy - floorf(gy);

    bool pos[5];
    pos[0] = true;
    pos[1] = (oi < 0.5f) && (gx > 1.0f);
    pos[2] = (oj < 0.5f) && (gy > 1.0f);
    pos[3] = (oi > 0.5f) && ((float)SDIM - gx > 1.0f);
    pos[4] = (oj > 0.5f) && ((float)SDIM - gy > 1.0f);
    const int di[5] = {0, -1, 0, 1, 0};
    const int dj[5] = {0, 0, -1, 0, 1};

    // anchors / stride for idx=0: (12,16),(19,36),(40,28) / 8
    const float aw[3] = {1.5f, 2.375f, 5.0f};
    const float ah[3] = {2.0f, 4.5f, 3.5f};
    float ww = bw * SDIM, hh = bh * SDIM;
    bool rm[3];
#pragma unroll
    for (int a = 0; a < 3; a++) {
        float rw = ww / aw[a], rh = hh / ah[a];
        float m = fmaxf(fmaxf(rw, 1.0f / rw), fmaxf(rh, 1.0f / rh));
        rm[a] = m < 4.0f;
    }

#pragma unroll
    for (int k = 0; k < 5; k++) {
        if (!pos[k]) continue;
        int ii = ib + di[k];
        int jj = jb + dj[k];
        if (ii < 0 || ii >= SDIM || jj < 0 || jj >= SDIM) continue;
#pragma unroll
        for (int a = 0; a < 3; a++) {
            if (!rm[a]) continue;
            int cell = ((b * NA + a) * SDIM + jj) * SDIM + ii;
            atomicMax(&g_win[cell], n * 5 + k);
        }
    }
}

// ---------------------------------------------------------------------------
__device__ __forceinline__ float softplusf(float x) {
    return fmaxf(x, 0.0f) + log1pf(expf(-fabsf(x)));
}

__device__ __forceinline__ float ciou_f(float x1, float y1, float w1, float h1,
                                        float x2, float y2, float w2, float h2) {
    float b1x1 = x1 - w1 * 0.5f, b1x2 = x1 + w1 * 0.5f;
    float b1y1 = y1 - h1 * 0.5f, b1y2 = y1 + h1 * 0.5f;
    float b2x1 = x2 - w2 * 0.5f, b2x2 = x2 + w2 * 0.5f;
    float b2y1 = y2 - h2 * 0.5f, b2y2 = y2 + h2 * 0.5f;

    float iw = fmaxf(fminf(b1x2, b2x2) - fmaxf(b1x1, b2x1), 0.0f);
    float ih = fmaxf(fminf(b1y2, b2y2) - fmaxf(b1y1, b2y1), 0.0f);
    float inter = iw * ih;
    float uni = w1 * h1 + w2 * h2 - inter + EPSF;
    float iou = inter / uni;

    float cw = fmaxf(b1x2, b2x2) - fminf(b1x1, b2x1);
    float ch = fmaxf(b1y2, b2y2) - fminf(b1y1, b2y1);
    float c2 = cw * cw + ch * ch + EPSF;
    float dx = (b2x1 + b2x2 - b1x1 - b1x2);
    float dy = (b2y1 + b2y2 - b1y1 - b1y2);
    float rho2 = (dx * dx + dy * dy) * 0.25f;

    const float K = 4.0f / (float)(M_PI * M_PI);
    float dv = atanf(w2 / (h2 + EPSF)) - atanf(w1 / (h1 + EPSF));
    float v = K * dv * dv;
    float alpha = v / (v - iou + (1.0f + EPSF));
    return iou - (rho2 / c2 + v * alpha);
}

// ---------------------------------------------------------------------------
// One thread per cell. Coalesced obj-plane read for all cells; full 85-ch
// gather + CIoU + 80-class BCE only on winner cells (~1-2K of 307200).
__global__ void loss_kernel(const float* __restrict__ preds,
                            const float* __restrict__ tg) {
    int cell = blockIdx.x * blockDim.x + threadIdx.x;
    float obj = 0.0f, clsum = 0.0f, boxsum = 0.0f, cnt = 0.0f;

    if (cell < NCELLS) {
        int i = cell % SDIM;
        int j = (cell / SDIM) % SDIM;
        int a = (cell / PLANE) % NA;
        int b = cell / (PLANE * NA);

        const float* pb = preds + ((long long)b * (NA * NCH) + a * NCH) * PLANE
                                + j * SDIM + i;
        float x4 = pb[4 * PLANE];
        float t2 = 0.0f;

        int w = g_win[cell];
        if (w >= 0) {
            int n = w / 5;
            const float* t = tg + n * 6;
            int   ci = (int)t[1];
            float tx = t[2], ty = t[3], tw = t[4], th = t[5];

            float p0 = pb[0];
            float p1 = pb[PLANE];
            float p2 = pb[2 * PLANE];
            float p3 = pb[3 * PLANE];

            const float AW[3] = {12.0f, 19.0f, 40.0f};
            const float AH[3] = {16.0f, 36.0f, 28.0f};
            float sx = 1.0f / (1.0f + expf(-p0));
            float sy = 1.0f / (1.0f + expf(-p1));
            float px = (sx * 2.0f - 0.5f + (float)i) / (float)SDIM;
            float py = (sy * 2.0f - 0.5f + (float)j) / (float)SDIM;
            float pw = expf(p2) * AW[a] / 640.0f;
            float ph = expf(p3) * AH[a] / 640.0f;

            float iou = ciou_f(px, py, pw, ph, tx, ty, tw, th);
            boxsum = 1.0f - iou;
            cnt = 1.0f;
            t2 = fmaxf(iou, 0.0f);

            float s = 0.0f;
#pragma unroll 4
            for (int c = 0; c < NCLS; c++) {
                float L = pb[(5 + c) * PLANE];
                // t==1: softplus(-L) = softplus(L) - L ; t==0: softplus(L)
                s += softplusf(L);
                if (c == ci) s -= L;
            }
            clsum = s;
        }
        obj = (1.0f - t2) * x4 + softplusf(-x4);
    }

    // block reduction of 4 partials
    float v0 = obj, v1 = clsum, v2 = boxsum, v3 = cnt;
#pragma unroll
    for (int off = 16; off > 0; off >>= 1) {
        v0 += __shfl_down_sync(0xffffffffu, v0, off);
        v1 += __shfl_down_sync(0xffffffffu, v1, off);
        v2 += __shfl_down_sync(0xffffffffu, v2, off);
        v3 += __shfl_down_sync(0xffffffffu, v3, off);
    }
    __shared__ float sh[4][8];  // up to 8 warps (256 threads)
    int lane = threadIdx.x & 31, warp = threadIdx.x >> 5;
    if (lane == 0) { sh[0][warp] = v0; sh[1][warp] = v1; sh[2][warp] = v2; sh[3][warp] = v3; }
    __syncthreads();
    if (warp == 0) {
        int nw = blockDim.x >> 5;
        float a0 = (lane < nw) ? sh[0][lane] : 0.0f;
        float a1 = (lane < nw) ? sh[1][lane] : 0.0f;
        float a2 = (lane < nw) ? sh[2][lane] : 0.0f;
        float a3 = (lane < nw) ? sh[3][lane] : 0.0f;
#pragma unroll
        for (int off = 4; off > 0; off >>= 1) {
            a0 += __shfl_down_sync(0xffffffffu, a0, off);
            a1 += __shfl_down_sync(0xffffffffu, a1, off);
            a2 += __shfl_down_sync(0xffffffffu, a2, off);
            a3 += __shfl_down_sync(0xffffffffu, a3, off);
        }
        if (lane == 0) {
            atomicAdd(&g_acc[0], (double)a0);
            atomicAdd(&g_acc[1], (double)a1);
            atomicAdd(&g_acc[2], (double)a2);
            atomicAdd(&g_acc[3], (double)a3);
        }
    }
}

// ---------------------------------------------------------------------------
__global__ void final_kernel(float* __restrict__ out) {
    double nobj  = g_acc[3];
    double denom = fmax(nobj, 1.0);
    bool   has   = nobj > 0.0;
    double lobj = g_acc[0] / (double)NCELLS;
    double lcls = has ? g_acc[1] / (denom * (double)NCLS) : 0.0;
    double lbox = has ? g_acc[2] / denom : 0.0;
    // OBJ_NORM=0.7, BALANCE[0]=4.0, CLS_NORM=0.3, IOU_NORM=0.05, nb=16
    out[0] = (float)(16.0 * (0.7 * 4.0 * lobj + 0.3 * lcls + 0.05 * lbox));
}

// ---------------------------------------------------------------------------
extern "C" void kernel_launch(void* const* d_in, const int* in_sizes, int n_in,
                              void* d_out, int out_size) {
    const float* preds   = (const float*)d_in[0];
    const float* targets = (const float*)d_in[1];
    int N = in_sizes[1] / 6;

    clear_kernel<<<(NCELLS + 255) / 256, 256>>>();
    scatter_kernel<<<(N + 63) / 64, 64>>>(targets, N);
    loss_kernel<<<(NCELLS + 255) / 256, 256>>>(preds, targets);
    final_kernel<<<1, 1>>>((float*)d_out);
}

// round 2
// speedup vs baseline: 1.6027x; 1.6027x over previous
#include <cuda_runtime.h>
#include <math.h>

#define SD 80
#define PLANE 6400
#define NCELLS 307200           // 16 * 3 * 80 * 80
#define EPSF 1e-7f
#define OBJ_BLOCKS 300
#define BLK 256

// Self-cleaning scratch: zero before first launch (static init), and the
// finalizing block resets everything to zero before the kernel exits.
__device__ double g_acc[4];     // 0: obj sum, 1: cls sum, 2: box sum, 3: nobj
__device__ int    g_done;

__device__ __forceinline__ float sp_fast(float x) {   // softplus(x)
    return fmaxf(x, 0.0f) + __logf(1.0f + __expf(-fabsf(x)));
}

__device__ __forceinline__ float ciou_f(float x1, float y1, float w1, float h1,
                                        float x2, float y2, float w2, float h2) {
    float b1x1 = x1 - w1 * 0.5f, b1x2 = x1 + w1 * 0.5f;
    float b1y1 = y1 - h1 * 0.5f, b1y2 = y1 + h1 * 0.5f;
    float b2x1 = x2 - w2 * 0.5f, b2x2 = x2 + w2 * 0.5f;
    float b2y1 = y2 - h2 * 0.5f, b2y2 = y2 + h2 * 0.5f;

    float iw = fmaxf(fminf(b1x2, b2x2) - fmaxf(b1x1, b2x1), 0.0f);
    float ih = fmaxf(fminf(b1y2, b2y2) - fmaxf(b1y1, b2y1), 0.0f);
    float inter = iw * ih;
    float uni = w1 * h1 + w2 * h2 - inter + EPSF;
    float iou = inter / uni;

    float cw = fmaxf(b1x2, b2x2) - fminf(b1x1, b2x1);
    float ch = fmaxf(b1y2, b2y2) - fminf(b1y1, b2y1);
    float c2 = cw * cw + ch * ch + EPSF;
    float dx = (b2x1 + b2x2 - b1x1 - b1x2);
    float dy = (b2y1 + b2y2 - b1y1 - b1y2);
    float rho2 = (dx * dx + dy * dy) * 0.25f;

    const float K = 4.0f / (float)(M_PI * M_PI);
    float dv = atanf(w2 / (h2 + EPSF)) - atanf(w1 / (h1 + EPSF));
    float v = K * dv * dv;
    float alpha = v / (v - iou + (1.0f + EPSF));
    return iou - (rho2 / c2 + v * alpha);
}

__global__ void __launch_bounds__(BLK)
fused_yolo_loss(const float* __restrict__ preds,
                const float* __restrict__ tg,
                int N, float* __restrict__ out) {
    const int tid = threadIdx.x;
    __shared__ float s_acc[4];
    if (tid < 4) s_acc[tid] = 0.0f;
    __syncthreads();

    if (blockIdx.x < OBJ_BLOCKS) {
        // ---- Objectness base sum: sum over all cells of softplus(x4) ----
        float s = 0.0f;
        for (int i = blockIdx.x * BLK + tid; i < NCELLS; i += OBJ_BLOCKS * BLK) {
            int sp = i % PLANE;
            int a  = (i / PLANE) % 3;
            int b  = i / (PLANE * 3);
            float x4 = preds[(size_t)((b * 3 + a) * 85 + 4) * PLANE + sp];
            s += sp_fast(x4);
        }
#pragma unroll
        for (int o = 16; o > 0; o >>= 1) s += __shfl_down_sync(0xffffffffu, s, o);
        if ((tid & 31) == 0) atomicAdd(&s_acc[0], s);
    } else {
        // ---- One warp per candidate scatter entry (n, k, a) ----
        const int lane  = tid & 31;
        const int wglob = (blockIdx.x - OBJ_BLOCKS) * (BLK >> 5) + (tid >> 5);
        const int NE    = N * 15;
        if (wglob < NE) {
            int n   = wglob / 15;
            int rem = wglob - n * 15;
            int k   = rem / 3;
            int a   = rem - k * 3;

            const float* t = tg + n * 6;
            int   b   = (int)t[0];
            int   cls = (int)t[1];
            float gx = t[2] * SD, gy = t[3] * SD;
            float ww = t[4] * SD, hh = t[5] * SD;
            float fib = floorf(gx), fjb = floorf(gy);
            float oi = gx - fib, oj = gy - fjb;

            bool posk = (k == 0)
                     || (k == 1 && oi < 0.5f && gx > 1.0f)
                     || (k == 2 && oj < 0.5f && gy > 1.0f)
                     || (k == 3 && oi > 0.5f && ((float)SD - gx) > 1.0f)
                     || (k == 4 && oj > 0.5f && ((float)SD - gy) > 1.0f);

            const float AWn[3] = {1.5f, 2.375f, 5.0f};   // anchors / stride, idx 0
            const float AHn[3] = {2.0f, 4.5f, 3.5f};
            float rw = ww / AWn[a], rh = hh / AHn[a];
            bool rm = fmaxf(fmaxf(rw, 1.0f / rw), fmaxf(rh, 1.0f / rh)) < 4.0f;

            if (posk && rm) {
                const int DI[5] = {0, -1, 0, 1, 0};
                const int DJ[5] = {0, 0, -1, 0, 1};
                int ii = (int)fib + DI[k];
                int jj = (int)fjb + DJ[k];

                // Scan later targets for same-cell collisions (same a, same b).
                bool cg = false;   // a later valid entry hits this cell (any class)
                bool cc = false;   // ... with the same class
                for (int n2 = n + 1 + lane; n2 < N; n2 += 32) {
                    const float* t2 = tg + n2 * 6;
                    if ((int)t2[0] != b) continue;
                    float ww2 = t2[4] * SD, hh2 = t2[5] * SD;
                    float rw2 = ww2 / AWn[a], rh2 = hh2 / AHn[a];
                    if (fmaxf(fmaxf(rw2, 1.0f / rw2), fmaxf(rh2, 1.0f / rh2)) >= 4.0f)
                        continue;
                    float gx2 = t2[2] * SD, gy2 = t2[3] * SD;
                    float fi2 = floorf(gx2), fj2 = floorf(gy2);
                    int ib2 = (int)fi2, jb2 = (int)fj2;
                    if (ib2 < ii - 1 || ib2 > ii + 1 || jb2 < jj - 1 || jb2 > jj + 1)
                        continue;
                    float oi2 = gx2 - fi2, oj2 = gy2 - fj2;
                    bool hit = (ib2 == ii && jb2 == jj);
                    hit |= (oi2 < 0.5f && gx2 > 1.0f               && ib2 - 1 == ii && jb2 == jj);
                    hit |= (oj2 < 0.5f && gy2 > 1.0f               && ib2 == ii && jb2 - 1 == jj);
                    hit |= (oi2 > 0.5f && ((float)SD - gx2) > 1.0f && ib2 + 1 == ii && jb2 == jj);
                    hit |= (oj2 > 0.5f && ((float)SD - gy2) > 1.0f && ib2 == ii && jb2 + 1 == jj);
                    if (hit) {
                        cg = true;
                        if ((int)t2[1] == cls) cc = true;
                    }
                }
                cg = __any_sync(0xffffffffu, cg);
                cc = __any_sync(0xffffffffu, cc);

                const float* pb = preds + (size_t)((b * 3 + a) * 85) * PLANE
                                        + jj * SD + ii;

                // cls: winner does the full softplus sum once per masked cell;
                // class-representative subtracts its logit once per (cell, class).
                float a1 = 0.0f;
                if (!cg) {
                    for (int c = lane; c < 80; c += 32)
                        a1 += sp_fast(pb[(5 + c) * PLANE]);
                }
                if (!cc && lane == 0)
                    a1 -= pb[(5 + cls) * PLANE];
#pragma unroll
                for (int o = 16; o > 0; o >>= 1)
                    a1 += __shfl_down_sync(0xffffffffu, a1, o);
                if (lane == 0 && a1 != 0.0f) atomicAdd(&s_acc[1], a1);

                if (!cg && lane == 0) {
                    float p0 = pb[0];
                    float p1 = pb[PLANE];
                    float p2 = pb[2 * PLANE];
                    float p3 = pb[3 * PLANE];
                    float x4 = pb[4 * PLANE];
                    const float AW[3] = {12.0f, 19.0f, 40.0f};
                    const float AH[3] = {16.0f, 36.0f, 28.0f};
                    float sx = 1.0f / (1.0f + __expf(-p0));
                    float sy = 1.0f / (1.0f + __expf(-p1));
                    float px = (sx * 2.0f - 0.5f + (float)ii) / (float)SD;
                    float py = (sy * 2.0f - 0.5f + (float)jj) / (float)SD;
                    float pw = __expf(p2) * AW[a] * (1.0f / 640.0f);
                    float ph = __expf(p3) * AH[a] * (1.0f / 640.0f);
                    float iou = ciou_f(px, py, pw, ph, t[2], t[3], t[4], t[5]);
                    atomicAdd(&s_acc[2], 1.0f - iou);
                    atomicAdd(&s_acc[3], 1.0f);
                    atomicAdd(&s_acc[0], -fmaxf(iou, 0.0f) * x4);  // obj correction
                }
            }
        }
    }

    __syncthreads();
    if (tid == 0) {
        if (s_acc[0] != 0.0f) atomicAdd(&g_acc[0], (double)s_acc[0]);
        if (s_acc[1] != 0.0f) atomicAdd(&g_acc[1], (double)s_acc[1]);
        if (s_acc[2] != 0.0f) atomicAdd(&g_acc[2], (double)s_acc[2]);
        if (s_acc[3] != 0.0f) atomicAdd(&g_acc[3], (double)s_acc[3]);
    }
    __threadfence();

    __shared__ int s_last;
    if (tid == 0) s_last = atomicAdd(&g_done, 1);
    __syncthreads();

    if (tid == 0 && s_last == (int)gridDim.x - 1) {
        // All other blocks' g_acc updates are visible (fence + atomic chain).
        double a0 = atomicAdd(&g_acc[0], 0.0);
        double a1 = atomicAdd(&g_acc[1], 0.0);
        double a2 = atomicAdd(&g_acc[2], 0.0);
        double a3 = atomicAdd(&g_acc[3], 0.0);

        double nobj  = a3;
        double denom = fmax(nobj, 1.0);
        bool   has   = nobj > 0.0;
        double lobj = a0 / (double)NCELLS;
        double lcls = has ? a1 / (denom * 80.0) : 0.0;
        double lbox = has ? a2 / denom : 0.0;
        // 16 * (OBJ_NORM*BALANCE0 * lobj + CLS_NORM * lcls + IOU_NORM * lbox)
        out[0] = (float)(16.0 * (2.8 * lobj + 0.3 * lcls + 0.05 * lbox));

        // Reset scratch for the next graph replay.
        g_acc[0] = 0.0; g_acc[1] = 0.0; g_acc[2] = 0.0; g_acc[3] = 0.0;
        g_done = 0;
    }
}

extern "C" void kernel_launch(void* const* d_in, const int* in_sizes, int n_in,
                              void* d_out, int out_size) {
    const float* preds   = (const float*)d_in[0];
    const float* targets = (const float*)d_in[1];
    int N = in_sizes[1] / 6;

    int entryBlocks = (N * 15 + (BLK / 32) - 1) / (BLK / 32);
    int grid = OBJ_BLOCKS + entryBlocks;
    fused_yolo_loss<<<grid, BLK>>>(preds, targets, N, (float*)d_out);
}